// round 15
// baseline (speedup 1.0000x reference)
#include <cuda_runtime.h>
#include <cuda_bf16.h>

// Problem constants (B=4, 96^3 vol, 4^3 patches, E=768)
#define TOKENS   13824
#define MASKN    10368
#define UNMASKN  3456
#define EDIM     768
#define KDIM     64
#define KPAIRS   96            // K' = 3*KDIM = 192 bf16 -> 96 bf16x2 pairs
#define KSTEPS   12
#define TT       48            // tokens per block (3 m16 bands)
#define NTHREADS 768
#define UT       (UNMASKN / TT)   // 72
#define MT       (MASKN / TT)     // 216
#define BATCH    4
#define AROW     100           // padded A' row stride (words)
#define BROW     776           // padded B row stride (words)
#define NJ       12            // n8 tiles per warp (96 dims, strided-12 mapping)
#define NSTAGE   4
#define STAGEB   (8 * BROW * 4)   // bytes per B stage = 24832
#define LOG2_1E4 13.287712379549449f

// dynamic smem layout (bytes)
#define AS_OFF   0                          // 48*100*4 = 19200
#define BS_OFF   19200                      // 4*24832 = 99328
#define SH_OFF   (BS_OFF + NSTAGE * STAGEB) // 118528
#define SW_OFF   (SH_OFF + 192)
#define SD_OFF   (SW_OFF + 192)
#define RS_OFF   (SD_OFF + 192)             // 48*9*4 = 1728
#define RQ_OFF   (RS_OFF + 1728)
#define MN_OFF   (RQ_OFF + 1728)
#define RV_OFF   (MN_OFF + 192)
#define SMEM_TOTAL (RV_OFF + 192)           // 122944

__device__ float g_pe[24][256];
// split weights, expanded K'=192, packed bf16x2 pairs: g_B2[p][e] = (B'[2p][e], B'[2p+1][e])
__device__ __align__(16) unsigned int g_B2[KPAIRS][EDIM];

__device__ __forceinline__ unsigned int bf16pair(float lo, float hi) {
    __nv_bfloat162 h = __floats2bfloat162_rn(lo, hi);
    return *reinterpret_cast<unsigned int*>(&h);
}

__device__ __forceinline__ void mma_bf16(float* c,
    unsigned int a0, unsigned int a1, unsigned int a2, unsigned int a3,
    unsigned int b0, unsigned int b1) {
    asm volatile(
        "mma.sync.aligned.m16n8k16.row.col.f32.bf16.bf16.f32 "
        "{%0,%1,%2,%3}, {%4,%5,%6,%7}, {%8,%9}, {%0,%1,%2,%3};"
        : "+f"(c[0]), "+f"(c[1]), "+f"(c[2]), "+f"(c[3])
        : "r"(a0), "r"(a1), "r"(a2), "r"(a3), "r"(b0), "r"(b1));
}

__device__ __forceinline__ void cpa16(unsigned int dst, const void* src) {
    asm volatile("cp.async.cg.shared.global [%0], [%1], 16;" :: "r"(dst), "l"(src));
}

__device__ __forceinline__ void ldsm_x4(unsigned int& a0, unsigned int& a1,
                                        unsigned int& a2, unsigned int& a3,
                                        unsigned int addr) {
    asm volatile("ldmatrix.sync.aligned.m8n8.x4.shared.b16 {%0,%1,%2,%3}, [%4];"
                 : "=r"(a0), "=r"(a1), "=r"(a2), "=r"(a3) : "r"(addr));
}

// ONE init kernel: blocks [0,24): pe table; [24,312): W split; [312,..): mask_idx tail.
__global__ __launch_bounds__(256)
void init_kernel(const float* __restrict__ W, const int* __restrict__ perm,
                 float* __restrict__ tail_out, int n_tail) {
    const int bi = blockIdx.x, tid = threadIdx.x;
    if (bi < 24) {
        const float invf = exp2f(-(float)(tid >> 1) * (LOG2_1E4 / 128.0f));
        float s, c;
        sincosf((float)bi * invf, &s, &c);
        g_pe[bi][tid] = (tid & 1) ? c : s;
    } else if (bi < 24 + 288) {
        const int idx = (bi - 24) * 256 + tid;
        const int p = idx / EDIM, e = idx % EDIM;
        float v[2];
        #pragma unroll
        for (int i = 0; i < 2; i++) {
            const int kp = 2 * p + i, m = kp / 3, r = kp - 3 * m;
            const float wv = W[m * EDIM + e];
            const float wh = __bfloat162float(__float2bfloat16_rn(wv));
            v[i] = (r == 1) ? (wv - wh) : wv;
        }
        g_B2[p][e] = bf16pair(v[0], v[1]);
    } else {
        const int i = (bi - 24 - 288) * 256 + tid;
        if (i < n_tail) tail_out[i] = (float)perm[i];
    }
}

// 48 tokens x 768 dims, bf16-split tensor MMA, fused bias/pe/LN.
// B frags: strided n-tile mapping -> 3+3 LDS.128/kstep. A frags: 1 ldmatrix.x4.
// 4-stage cp.async ring, prefetch distance 2, one barrier per kstep.
__global__ __launch_bounds__(NTHREADS, 1)
void embed_kernel(const float* __restrict__ x,
                  const float* __restrict__ bias,
                  const float* __restrict__ mtok,
                  const float* __restrict__ gamma,
                  const float* __restrict__ beta,
                  const int*   __restrict__ perm,
                  float* __restrict__ out)
{
    extern __shared__ __align__(16) char smem[];
    unsigned int (*As)[AROW] = (unsigned int (*)[AROW])(smem + AS_OFF);
    int*   sH    = (int*)(smem + SH_OFF);
    int*   sW    = (int*)(smem + SW_OFF);
    int*   sD    = (int*)(smem + SD_OFF);
    float (*redS)[9] = (float (*)[9])(smem + RS_OFF);
    float (*redQ)[9] = (float (*)[9])(smem + RQ_OFF);
    float* meanv = (float*)(smem + MN_OFF);
    float* rstdv = (float*)(smem + RV_OFF);
    const unsigned int smem_u32 = (unsigned int)__cvta_generic_to_shared(smem);
    const unsigned int bs_base  = smem_u32 + BS_OFF;

    const int tid  = threadIdx.x;
    const int lane = tid & 31;
    const int w    = tid >> 5;
    const int g    = lane >> 2;
    const int tg   = lane & 3;
    const int band = w >> 3;
    const int dg   = w & 7;

    const int bi = blockIdx.x;
    const bool is_mask = bi >= BATCH * UT;
    int b = 0, tile;
    if (!is_mask) { b = bi / UT; tile = bi % UT; }
    else          { tile = bi - BATCH * UT; }

    // C-fragment physical columns: run0 = ebase0 + j, run1 = ebase0 + 12 + j (j=0..11)
    const int ebase0 = dg * 96 + 24 * tg;
    const int ebase1 = ebase0 + 12;

    // ---- acc init with bias ----
    float acc[NJ][4];
    #pragma unroll
    for (int q = 0; q < 3; q++) {
        const float4 b0v = *(const float4*)(bias + ebase0 + 4 * q);
        const float4 b1v = *(const float4*)(bias + ebase1 + 4 * q);
        const float bb0[4] = {b0v.x, b0v.y, b0v.z, b0v.w};
        const float bb1[4] = {b1v.x, b1v.y, b1v.z, b1v.w};
        #pragma unroll
        for (int i = 0; i < 4; i++) {
            acc[4 * q + i][0] = bb0[i]; acc[4 * q + i][1] = bb1[i];
            acc[4 * q + i][2] = bb0[i]; acc[4 * q + i][3] = bb1[i];
        }
    }

    // ---- B staging addresses: 1536 uint4/kstep, 2 per thread ----
    const int r0 = tid / 192, c0 = (tid % 192) * 4;
    const unsigned int d0 = (unsigned int)(((r0)     * BROW + c0) * 4);
    const unsigned int d1 = (unsigned int)(((r0 + 4) * BROW + c0) * 4);

    // prologue: groups 0 and 1 into stages 0,1
    cpa16(bs_base + d0, &g_B2[r0][c0]);
    cpa16(bs_base + d1, &g_B2[r0 + 4][c0]);
    asm volatile("cp.async.commit_group;");
    cpa16(bs_base + STAGEB + d0, &g_B2[8 + r0][c0]);
    cpa16(bs_base + STAGEB + d1, &g_B2[8 + r0 + 4][c0]);
    asm volatile("cp.async.commit_group;");

    // ---- stage A': 48 tokens x 16 segs, bf16-split, K'=192 ----
    {
        const int tok = tid % 48;
        const int seg = tid / 48;
        const int m   = tile * TT + tok;
        const int s   = is_mask ? perm[m] : perm[MASKN + m];
        const int h = s / 576, wq = (s % 576) / 24, d = s % 24;
        if (seg == 0) { sH[tok] = h; sW[tok] = wq; sD[tok] = d; }
        float4 v;
        if (!is_mask) {
            const int i = seg >> 2, j = seg & 3;
            const size_t xi = (((size_t)(b * 96 + 4 * h + i)) * 96 + (4 * wq + j)) * 96 + 4 * d;
            v = *(const float4*)(x + xi);
        } else {
            v = *(const float4*)(mtok + (size_t)m * KDIM + seg * 4);
        }
        const float f0 = v.x, f1 = v.y, f2 = v.z, f3 = v.w;
        const float h0 = __bfloat162float(__float2bfloat16_rn(f0));
        const float h1 = __bfloat162float(__float2bfloat16_rn(f1));
        const float h2 = __bfloat162float(__float2bfloat16_rn(f2));
        const float h3 = __bfloat162float(__float2bfloat16_rn(f3));
        unsigned int* ar = &As[tok][6 * seg];
        ar[0] = bf16pair(f0,      f0);
        ar[1] = bf16pair(f0 - h0, f1);
        ar[2] = bf16pair(f1,      f1 - h1);
        ar[3] = bf16pair(f2,      f2);
        ar[4] = bf16pair(f2 - h2, f3);
        ar[5] = bf16pair(f3,      f3 - h3);
    }

    // ldmatrix lane address (row fixed, k-chunk advances with ks)
    const unsigned int a_row_addr =
        smem_u32 + AS_OFF +
        (unsigned int)(((band * 16 + (lane & 15)) * AROW + ((lane >> 4) << 2)) * 4);

    // B fragment word offsets (uint4 index): tg*194 + dg*24 + g*3  (+4*194 for b1)
    const int bchunk0 = tg * 194 + dg * 24 + g * 3;
    const int bchunk1 = bchunk0 + 4 * 194;

    const int t0 = band * 16 + g, t1 = t0 + 8;

    // ---- GEMM main loop ----
    #pragma unroll 1
    for (int ks = 0; ks < KSTEPS; ks++) {
        if (ks + 2 < KSTEPS) {
            const unsigned int sb = bs_base + ((ks + 2) % NSTAGE) * STAGEB;
            cpa16(sb + d0, &g_B2[8 * (ks + 2) + r0][c0]);
            cpa16(sb + d1, &g_B2[8 * (ks + 2) + r0 + 4][c0]);
            asm volatile("cp.async.commit_group;");
            asm volatile("cp.async.wait_group 2;");
        } else if (ks + 1 < KSTEPS) {
            asm volatile("cp.async.wait_group 1;");
        } else {
            asm volatile("cp.async.wait_group 0;");
        }
        __syncthreads();

        unsigned int a0, a1, a2, a3;
        ldsm_x4(a0, a1, a2, a3, a_row_addr + (unsigned int)(32 * ks));

        const uint4* Bst = (const uint4*)(smem + BS_OFF + (ks % NSTAGE) * STAGEB);
        const uint4 b0a = Bst[bchunk0], b0b = Bst[bchunk0 + 1], b0c = Bst[bchunk0 + 2];
        const uint4 b1a = Bst[bchunk1], b1b = Bst[bchunk1 + 1], b1c = Bst[bchunk1 + 2];

        mma_bf16(acc[0],  a0, a1, a2, a3, b0a.x, b1a.x);
        mma_bf16(acc[1],  a0, a1, a2, a3, b0a.y, b1a.y);
        mma_bf16(acc[2],  a0, a1, a2, a3, b0a.z, b1a.z);
        mma_bf16(acc[3],  a0, a1, a2, a3, b0a.w, b1a.w);
        mma_bf16(acc[4],  a0, a1, a2, a3, b0b.x, b1b.x);
        mma_bf16(acc[5],  a0, a1, a2, a3, b0b.y, b1b.y);
        mma_bf16(acc[6],  a0, a1, a2, a3, b0b.z, b1b.z);
        mma_bf16(acc[7],  a0, a1, a2, a3, b0b.w, b1b.w);
        mma_bf16(acc[8],  a0, a1, a2, a3, b0c.x, b1c.x);
        mma_bf16(acc[9],  a0, a1, a2, a3, b0c.y, b1c.y);
        mma_bf16(acc[10], a0, a1, a2, a3, b0c.z, b1c.z);
        mma_bf16(acc[11], a0, a1, a2, a3, b0c.w, b1c.w);
    }

    // ---- epilogue: + pe (scalar, seg-aware), LN stats ----
    const int h0s = sH[t0], w0s = sW[t0], d0s = sD[t0];
    const int h1s = sH[t1], w1s = sW[t1], d1s = sD[t1];
    float s0 = 0.f, q0 = 0.f, s1 = 0.f, q1 = 0.f;
    #pragma unroll
    for (int j = 0; j < NJ; j++) {
        const int e0 = ebase0 + j, e1 = ebase1 + j;
        const int sg0 = e0 >> 8, sg1 = e1 >> 8;
        const int p00 = (sg0 == 0) ? h0s : (sg0 == 1) ? w0s : d0s;
        const int p01 = (sg1 == 0) ? h0s : (sg1 == 1) ? w0s : d0s;
        const int p10 = (sg0 == 0) ? h1s : (sg0 == 1) ? w1s : d1s;
        const int p11 = (sg1 == 0) ? h1s : (sg1 == 1) ? w1s : d1s;
        acc[j][0] += __ldg(&g_pe[p00][e0 & 255]);
        acc[j][1] += __ldg(&g_pe[p01][e1 & 255]);
        acc[j][2] += __ldg(&g_pe[p10][e0 & 255]);
        acc[j][3] += __ldg(&g_pe[p11][e1 & 255]);
        s0 += acc[j][0] + acc[j][1];
        q0 += acc[j][0] * acc[j][0] + acc[j][1] * acc[j][1];
        s1 += acc[j][2] + acc[j][3];
        q1 += acc[j][2] * acc[j][2] + acc[j][3] * acc[j][3];
    }
    #pragma unroll
    for (int off = 1; off <= 2; off <<= 1) {
        s0 += __shfl_xor_sync(0xffffffffu, s0, off);
        q0 += __shfl_xor_sync(0xffffffffu, q0, off);
        s1 += __shfl_xor_sync(0xffffffffu, s1, off);
        q1 += __shfl_xor_sync(0xffffffffu, q1, off);
    }
    if (tg == 0) {
        redS[t0][dg] = s0; redQ[t0][dg] = q0;
        redS[t1][dg] = s1; redQ[t1][dg] = q1;
    }
    __syncthreads();

    if (tid < TT) {
        float sm = 0.f, sq = 0.f;
        #pragma unroll
        for (int wi = 0; wi < 8; wi++) { sm += redS[tid][wi]; sq += redQ[tid][wi]; }
        const float mn = sm * (1.0f / (float)EDIM);
        const float vr = sq * (1.0f / (float)EDIM) - mn * mn;
        meanv[tid] = mn;
        rstdv[tid] = rsqrtf(vr + 0.001f);
    }
    __syncthreads();

    const float mn0 = meanv[t0], rs0 = rstdv[t0];
    const float mn1 = meanv[t1], rs1 = rstdv[t1];

    // ---- stores: 4 runs x 3 STG.128 (runs are 12 consecutive cols) ----
    const size_t obase = is_mask ? (size_t)(UNMASKN + tile * TT)
                                 : ((size_t)b * TOKENS + (size_t)tile * TT);
    float* o0 = out + (obase + t0) * EDIM;
    float* o1 = out + (obase + t1) * EDIM;
    const size_t bstride = (size_t)TOKENS * EDIM;

    #pragma unroll
    for (int run = 0; run < 4; run++) {
        const int eb = (run & 1) ? ebase1 : ebase0;
        float* op = (run < 2) ? o0 : o1;
        const float mn = (run < 2) ? mn0 : mn1;
        const float rs = (run < 2) ? rs0 : rs1;
        const int ai = run;   // acc[.][run] holds (token, col-run) per mapping
        #pragma unroll
        for (int q = 0; q < 3; q++) {
            const float4 gm = *(const float4*)(gamma + eb + 4 * q);
            const float4 bt = *(const float4*)(beta + eb + 4 * q);
            float4 r;
            r.x = (acc[4 * q + 0][ai] - mn) * rs * gm.x + bt.x;
            r.y = (acc[4 * q + 1][ai] - mn) * rs * gm.y + bt.y;
            r.z = (acc[4 * q + 2][ai] - mn) * rs * gm.z + bt.z;
            r.w = (acc[4 * q + 3][ai] - mn) * rs * gm.w + bt.w;
            if (!is_mask) {
                *(float4*)(op + eb + 4 * q) = r;
            } else {
                #pragma unroll
                for (int bb = 0; bb < BATCH; bb++)
                    *(float4*)(op + bb * bstride + eb + 4 * q) = r;
            }
        }
    }
}

extern "C" void kernel_launch(void* const* d_in, const int* in_sizes, int n_in,
                              void* d_out, int out_size) {
    const float* x     = (const float*)d_in[0];
    const float* W     = (const float*)d_in[1];
    const float* bias  = (const float*)d_in[2];
    const float* mtok  = (const float*)d_in[3];
    const float* gamma = (const float*)d_in[4];
    const float* beta  = (const float*)d_in[5];
    const int*   perm  = (const int*)d_in[6];
    float* out = (float*)d_out;

    const long long main_elems = (long long)BATCH * TOKENS * EDIM;  // 42,467,328
    const long long extra = (long long)out_size - main_elems;       // expected 10368 (mask_idx)
    const int n_tail = extra > 0 ? (int)extra : 0;
    const int tail_blocks = (n_tail + 255) / 256;

    cudaFuncSetAttribute(embed_kernel,
                         cudaFuncAttributeMaxDynamicSharedMemorySize, SMEM_TOTAL);

    init_kernel<<<24 + 288 + tail_blocks, 256>>>(W, perm, out + main_elems, n_tail);

    embed_kernel<<<BATCH * UT + MT, NTHREADS, SMEM_TOTAL>>>(
        x, bias, mtok, gamma, beta, perm, out);
}

// round 16
// speedup vs baseline: 1.3970x; 1.3970x over previous
#include <cuda_runtime.h>

// Problem constants (B=4, 96^3 vol, 4^3 patches, E=768)
#define TOKENS   13824
#define MASKN    10368
#define UNMASKN  3456
#define EDIM     768
#define KDIM     64
#define TT       16         // tokens per block
#define NTHREADS 192        // 192 threads x 4 consecutive dims = 768
#define NW       6          // warps per block
#define UTILES   (UNMASKN / TT)   // 216
#define MTILES   (MASKN / TT)     // 648
#define BATCH    4
#define PSROW    20         // padded ps row (floats)
#define LOG2_1E4 13.287712379549449f

// positional-encoding table: g_pe[pos][c] = (c even ? sin : cos)(pos * 10000^-((c>>1)/128))
__device__ float g_pe[24][256];

__device__ __forceinline__ unsigned long long pack2(float a) {
    unsigned long long r;
    asm("mov.b64 %0, {%1, %1};" : "=l"(r) : "f"(a));
    return r;
}
__device__ __forceinline__ unsigned long long pack2b(float lo, float hi) {
    unsigned long long r;
    asm("mov.b64 %0, {%1, %2};" : "=l"(r) : "f"(lo), "f"(hi));
    return r;
}
__device__ __forceinline__ void fma2(unsigned long long& acc,
                                     unsigned long long a, unsigned long long b) {
    asm("fma.rn.f32x2 %0, %1, %2, %0;" : "+l"(acc) : "l"(a), "l"(b));
}
__device__ __forceinline__ void unpack2(unsigned long long v, float& lo, float& hi) {
    asm("mov.b64 {%0, %1}, %2;" : "=f"(lo), "=f"(hi) : "l"(v));
}

// Blocks [0,24): fill pe table row = blockIdx.x. Blocks [24,..): write mask_idx tail.
__global__ __launch_bounds__(256)
void init_pe_kernel(const int* __restrict__ perm, float* __restrict__ tail_out, int n_tail) {
    const int bi = blockIdx.x, tid = threadIdx.x;
    if (bi < 24) {
        const float invf = exp2f(-(float)(tid >> 1) * (LOG2_1E4 / 128.0f));
        float s, c;
        sincosf((float)bi * invf, &s, &c);
        g_pe[bi][tid] = (tid & 1) ? c : s;
    } else {
        const int i = (bi - 24) * 256 + tid;
        if (i < n_tail) tail_out[i] = (float)perm[i];
    }
}

// One block = 16 tokens x 768 dims. Thread owns dims 4*tid..4*tid+3 (one pe segment).
// TWO-PASS epilogue streams over acc (no duplicate v[] array) -> max live ~84 regs
// -> 4 blocks/SM = 24 warps at R4's measured-best instruction economy.
// Blocks [0, 864): unmask per batch. Blocks [864, 1512): mask tokens,
// computed once, written to all 4 batches (batch-invariant incl. LN).
__global__ __launch_bounds__(NTHREADS, 4)
void embed_kernel(const float* __restrict__ x,
                  const float* __restrict__ W,
                  const float* __restrict__ bias,
                  const float* __restrict__ mtok,
                  const float* __restrict__ gamma,
                  const float* __restrict__ beta,
                  const int*   __restrict__ perm,
                  float* __restrict__ out)
{
    __shared__ float ps[KDIM][PSROW];       // patch tile, k-major; token pairs contiguous
    __shared__ int   sH[TT], sW[TT], sD[TT];
    __shared__ float redS[TT][NW + 1], redQ[TT][NW + 1];
    __shared__ float meanv[TT], rstdv[TT];

    const int tid = threadIdx.x;
    const int bi  = blockIdx.x;
    const bool is_mask = bi >= BATCH * UTILES;
    int b = 0, tile;
    if (!is_mask) { b = bi / UTILES; tile = bi % UTILES; }
    else          { tile = bi - BATCH * UTILES; }

    // ---- stage: gather 16 patch rows (64 floats each) into SMEM ----
    for (int it = tid; it < TT * 16; it += NTHREADS) {
        const int tok = it & 15;      // consecutive lanes -> consecutive tokens
        const int seg = it >> 4;      // 0..15 -> 4 floats each
        const int m   = tile * TT + tok;
        const int s   = is_mask ? perm[m] : perm[MASKN + m];
        const int h = s / 576, w = (s % 576) / 24, d = s % 24;
        if (seg == 0) { sH[tok] = h; sW[tok] = w; sD[tok] = d; }
        float4 v;
        if (!is_mask) {
            const int i = seg >> 2, j = seg & 3;
            const size_t xi = (((size_t)(b * 96 + 4 * h + i)) * 96 + (4 * w + j)) * 96 + 4 * d;
            v = *(const float4*)(x + xi);
        } else {
            v = *(const float4*)(mtok + (size_t)m * KDIM + seg * 4);
        }
        const int p = seg * 4;
        ps[p + 0][tok] = v.x; ps[p + 1][tok] = v.y;
        ps[p + 2][tok] = v.z; ps[p + 3][tok] = v.w;
    }
    __syncthreads();

    // ---- GEMM: thread owns 4 consecutive dims; accumulators = token pairs (f32x2) ----
    unsigned long long a0[8], a1[8], a2[8], a3[8];
    {
        const float4 b4 = *((const float4*)bias + tid);
        const unsigned long long B0 = pack2(b4.x), B1 = pack2(b4.y),
                                 B2 = pack2(b4.z), B3 = pack2(b4.w);
        #pragma unroll
        for (int t = 0; t < 8; t++) { a0[t] = B0; a1[t] = B1; a2[t] = B2; a3[t] = B3; }
    }

    const float4* wp4 = (const float4*)W + tid;
    #pragma unroll 2
    for (int k = 0; k < KDIM; k++) {
        const float4 w4 = wp4[k * (EDIM / 4)];
        const unsigned long long W0 = pack2(w4.x), W1 = pack2(w4.y),
                                 W2 = pack2(w4.z), W3 = pack2(w4.w);
        const ulonglong2* pp2 = (const ulonglong2*)ps[k];   // broadcast LDS.128
        #pragma unroll
        for (int q = 0; q < 4; q++) {
            const ulonglong2 pd = pp2[q];
            fma2(a0[2 * q],     pd.x, W0);
            fma2(a1[2 * q],     pd.x, W1);
            fma2(a2[2 * q],     pd.x, W2);
            fma2(a3[2 * q],     pd.x, W3);
            fma2(a0[2 * q + 1], pd.y, W0);
            fma2(a1[2 * q + 1], pd.y, W1);
            fma2(a2[2 * q + 1], pd.y, W2);
            fma2(a3[2 * q + 1], pd.y, W3);
        }
    }

    // thread's 4 dims live in exactly one pe segment: tid<64 -> H, <128 -> W, else D
    const int* sposArr = (tid < 64) ? sH : (tid < 128) ? sW : sD;
    const int pecol = (tid & 63) * 4;
    const int warp = tid >> 5, lane = tid & 31;

    // ---- epilogue PASS 1: stream over acc pairs: +pe (repacked in place), LN stats ----
    #pragma unroll
    for (int t2 = 0; t2 < 8; t2++) {
        const int ta = 2 * t2, tb = ta + 1;
        float x0a, x0b, x1a, x1b, x2a, x2b, x3a, x3b;
        unpack2(a0[t2], x0a, x0b);
        unpack2(a1[t2], x1a, x1b);
        unpack2(a2[t2], x2a, x2b);
        unpack2(a3[t2], x3a, x3b);
        const float4 pa = __ldg((const float4*)&g_pe[sposArr[ta]][pecol]);
        const float4 pb = __ldg((const float4*)&g_pe[sposArr[tb]][pecol]);
        x0a += pa.x; x1a += pa.y; x2a += pa.z; x3a += pa.w;
        x0b += pb.x; x1b += pb.y; x2b += pb.z; x3b += pb.w;
        a0[t2] = pack2b(x0a, x0b);
        a1[t2] = pack2b(x1a, x1b);
        a2[t2] = pack2b(x2a, x2b);
        a3[t2] = pack2b(x3a, x3b);

        float sma = x0a + x1a + x2a + x3a;
        float sqa = x0a * x0a + x1a * x1a + x2a * x2a + x3a * x3a;
        float smb = x0b + x1b + x2b + x3b;
        float sqb = x0b * x0b + x1b * x1b + x2b * x2b + x3b * x3b;
        #pragma unroll
        for (int off = 16; off > 0; off >>= 1) {
            sma += __shfl_xor_sync(0xffffffffu, sma, off);
            sqa += __shfl_xor_sync(0xffffffffu, sqa, off);
            smb += __shfl_xor_sync(0xffffffffu, smb, off);
            sqb += __shfl_xor_sync(0xffffffffu, sqb, off);
        }
        if (lane == 0) {
            redS[ta][warp] = sma; redQ[ta][warp] = sqa;
            redS[tb][warp] = smb; redQ[tb][warp] = sqb;
        }
    }
    __syncthreads();

    if (tid < TT) {
        float sm = 0.f, sq = 0.f;
        #pragma unroll
        for (int wi = 0; wi < NW; wi++) { sm += redS[tid][wi]; sq += redQ[tid][wi]; }
        const float mn = sm * (1.0f / (float)EDIM);
        const float vr = sq * (1.0f / (float)EDIM) - mn * mn;
        meanv[tid] = mn;
        rstdv[tid] = rsqrtf(vr + 0.001f);
    }
    __syncthreads();

    // ---- epilogue PASS 2: normalize + store (unpack acc again; pe already added) ----
    const float4 g4  = *((const float4*)gamma + tid);
    const float4 be4 = *((const float4*)beta + tid);

    if (!is_mask) {
        float4* o = (float4*)(out + ((size_t)b * TOKENS + (size_t)tile * TT) * EDIM) + tid;
        #pragma unroll
        for (int t2 = 0; t2 < 8; t2++) {
            const int ta = 2 * t2, tb = ta + 1;
            float x0a, x0b, x1a, x1b, x2a, x2b, x3a, x3b;
            unpack2(a0[t2], x0a, x0b);
            unpack2(a1[t2], x1a, x1b);
            unpack2(a2[t2], x2a, x2b);
            unpack2(a3[t2], x3a, x3b);
            const float mna = meanv[ta], rsa = rstdv[ta];
            const float mnb = meanv[tb], rsb = rstdv[tb];
            float4 ra, rb;
            ra.x = (x0a - mna) * rsa * g4.x + be4.x;
            ra.y = (x1a - mna) * rsa * g4.y + be4.y;
            ra.z = (x2a - mna) * rsa * g4.z + be4.z;
            ra.w = (x3a - mna) * rsa * g4.w + be4.w;
            rb.x = (x0b - mnb) * rsb * g4.x + be4.x;
            rb.y = (x1b - mnb) * rsb * g4.y + be4.y;
            rb.z = (x2b - mnb) * rsb * g4.z + be4.z;
            rb.w = (x3b - mnb) * rsb * g4.w + be4.w;
            o[(size_t)ta * (EDIM / 4)] = ra;
            o[(size_t)tb * (EDIM / 4)] = rb;
        }
    } else {
        float4* o = (float4*)(out + ((size_t)UNMASKN + (size_t)tile * TT) * EDIM) + tid;
        const size_t bstride = (size_t)TOKENS * (EDIM / 4);
        #pragma unroll
        for (int t2 = 0; t2 < 8; t2++) {
            const int ta = 2 * t2, tb = ta + 1;
            float x0a, x0b, x1a, x1b, x2a, x2b, x3a, x3b;
            unpack2(a0[t2], x0a, x0b);
            unpack2(a1[t2], x1a, x1b);
            unpack2(a2[t2], x2a, x2b);
            unpack2(a3[t2], x3a, x3b);
            const float mna = meanv[ta], rsa = rstdv[ta];
            const float mnb = meanv[tb], rsb = rstdv[tb];
            float4 ra, rb;
            ra.x = (x0a - mna) * rsa * g4.x + be4.x;
            ra.y = (x1a - mna) * rsa * g4.y + be4.y;
            ra.z = (x2a - mna) * rsa * g4.z + be4.z;
            ra.w = (x3a - mna) * rsa * g4.w + be4.w;
            rb.x = (x0b - mnb) * rsb * g4.x + be4.x;
            rb.y = (x1b - mnb) * rsb * g4.y + be4.y;
            rb.z = (x2b - mnb) * rsb * g4.z + be4.z;
            rb.w = (x3b - mnb) * rsb * g4.w + be4.w;
            float4* oa = o + (size_t)ta * (EDIM / 4);
            float4* ob = o + (size_t)tb * (EDIM / 4);
            #pragma unroll
            for (int bb = 0; bb < BATCH; bb++) {
                oa[bb * bstride] = ra;
                ob[bb * bstride] = rb;
            }
        }
    }
}

extern "C" void kernel_launch(void* const* d_in, const int* in_sizes, int n_in,
                              void* d_out, int out_size) {
    const float* x     = (const float*)d_in[0];
    const float* W     = (const float*)d_in[1];
    const float* bias  = (const float*)d_in[2];
    const float* mtok  = (const float*)d_in[3];
    const float* gamma = (const float*)d_in[4];
    const float* beta  = (const float*)d_in[5];
    const int*   perm  = (const int*)d_in[6];
    float* out = (float*)d_out;

    const long long main_elems = (long long)BATCH * TOKENS * EDIM;  // 42,467,328
    const long long extra = (long long)out_size - main_elems;       // expected 10368 (mask_idx)
    const int n_tail = extra > 0 ? (int)extra : 0;
    const int tail_blocks = (n_tail + 255) / 256;

    // init: pe table (24 blocks) + mask_idx tail writes
    init_pe_kernel<<<24 + tail_blocks, 256>>>(perm, out + main_elems, n_tail);

    embed_kernel<<<BATCH * UTILES + MTILES, NTHREADS>>>(x, W, bias, mtok, gamma, beta, perm, out);
}